// round 16
// baseline (speedup 1.0000x reference)
#include <cuda_runtime.h>
#include <cstdint>

// x (8, 3, 65536) f32 -> out (8, 3, 512) f32, farthest point sampling.
// 128 plain CTAs (8 batches x 16), inter-CTA sync via self-validating L2 mailbox.
#define BATCHES 8
#define NPTS    65536
#define MOUT    512
#define CPB     16                        // CTAs per batch
#define TPB     256
#define NWARPS  (TPB / 32)
#define TPBATCH (CPB * TPB)               // 4096 threads per batch
#define PPT     (NPTS / TPBATCH)          // 16 points per thread
#define PAIRS   (PPT / 2)                 // 8 packed f32x2 pairs

typedef unsigned long long u64;
typedef unsigned int u32;

// Mailbox: one u64 slot per (batch, parity, cta):
//   v = distbits(32) | ni16(16) | tag(16),  ni16 = (~idx)&0xFFFF, tag = j&0xFFFF.
// Self-validating single 8B access: no ordering primitives needed. Zero-init at
// load; stale cross-launch values are bit-identical by determinism.
__device__ u64 g_slots[BATCHES][2][CPB];

// ---- packed f32x2 math (per-lane IEEE .rn, bit-identical to scalar) ----
__device__ __forceinline__ u64 f2pack(float lo, float hi) {
    u64 r; asm("mov.b64 %0, {%1, %2};" : "=l"(r) : "f"(lo), "f"(hi)); return r;
}
__device__ __forceinline__ void f2unpack(float& lo, float& hi, u64 v) {
    asm("mov.b64 {%0, %1}, %2;" : "=f"(lo), "=f"(hi) : "l"(v));
}
__device__ __forceinline__ u64 f2add(u64 a, u64 b) {
    u64 r; asm("add.rn.f32x2 %0, %1, %2;" : "=l"(r) : "l"(a), "l"(b)); return r;
}
__device__ __forceinline__ u64 f2mul(u64 a, u64 b) {
    u64 r; asm("mul.rn.f32x2 %0, %1, %2;" : "=l"(r) : "l"(a), "l"(b)); return r;
}

__global__ void __launch_bounds__(TPB, 1)
fps_kernel(const float* __restrict__ x, float* __restrict__ out)
{
    __shared__ u64 s_wkey[NWARPS];          // per-warp winners (intra-CTA funnel)

    const int b    = blockIdx.x >> 4;       // batch
    const int c    = blockIdx.x & 15;       // CTA within batch
    const int tid  = threadIdx.x;
    const int lane = tid & 31;
    const int warp = tid >> 5;
    const int tcl  = c * TPB + tid;         // 0..4095 within batch

    const float* __restrict__ xb = x + (size_t)b * 3 * NPTS;
    float* __restrict__ ob       = out + (size_t)b * 3 * MOUT;

    // Register-resident points (packed pairs) + running min distance
    u64 px2[PAIRS], py2[PAIRS], pz2[PAIRS];
    float dist[PPT];
#pragma unroll
    for (int i = 0; i < PAIRS; i++) {
        int k0 = 2 * i, k1 = 2 * i + 1;
        int g0 = k0 * TPBATCH + tcl, g1 = k1 * TPBATCH + tcl;   // coalesced
        px2[i] = f2pack(__ldg(xb + g0),            __ldg(xb + g1));
        py2[i] = f2pack(__ldg(xb + NPTS + g0),     __ldg(xb + NPTS + g1));
        pz2[i] = f2pack(__ldg(xb + 2 * NPTS + g0), __ldg(xb + 2 * NPTS + g1));
        dist[k0] = INFINITY;
        dist[k1] = INFINITY;
    }

    // First centroid is point 0 (standard PointNet++ convention)
    float cx = __ldg(xb);
    float cy = __ldg(xb + NPTS);
    float cz = __ldg(xb + 2 * NPTS);
    if (c == 0 && tid == 0) {
        ob[0]        = cx;
        ob[MOUT]     = cy;
        ob[2 * MOUT] = cz;
    }

    for (int j = 1; j < MOUT; j++) {
        // ---- pass 1: packed distance update. Per-lane .rn arithmetic, same
        //      order as reference: (dx*dx + dy*dy) + dz*dz. Track max only. ----
        u64 ncx = f2pack(-cx, -cx);
        u64 ncy = f2pack(-cy, -cy);
        u64 ncz = f2pack(-cz, -cz);
        float best = -1.0f;
#pragma unroll
        for (int i = 0; i < PAIRS; i++) {
            u64 dx = f2add(px2[i], ncx);
            u64 dy = f2add(py2[i], ncy);
            u64 dz = f2add(pz2[i], ncz);
            u64 s  = f2add(f2mul(dx, dx), f2mul(dy, dy));
            u64 dd = f2add(s, f2mul(dz, dz));
            float e0, e1;
            f2unpack(e0, e1, dd);
            float n0 = fminf(dist[2 * i],     e0);
            float n1 = fminf(dist[2 * i + 1], e1);
            dist[2 * i]     = n0;
            dist[2 * i + 1] = n1;
            best = fmaxf(best, fmaxf(n0, n1));
        }

        // ---- pass 2: min k among dist[k]==best (first-occurrence argmax) ----
        int kb = 0x7FFFFFFF;
#pragma unroll
        for (int k = 0; k < PPT; k++) {
            if (dist[k] == best) kb = min(kb, k);
        }
        u32 bidx = (u32)(kb * TPBATCH + tcl);       // < 65536 (16 bits)

        // ---- warp reduce via REDUX (R14-proven): max dist bits (sq dists
        //      >= 0 so u32 order == float order), then min index among ties ----
        u32 dbits = __float_as_uint(best);
        u32 wmax  = __reduce_max_sync(0xFFFFFFFFu, dbits);
        u32 cnd   = (dbits == wmax) ? bidx : 0xFFFFFFFFu;
        u32 wmin  = __reduce_min_sync(0xFFFFFFFFu, cnd);
        if (lane == 0)
            s_wkey[warp] = ((u64)wmax << 32) | (u32)~wmin;
        __syncthreads();

        // ---- CTA reduce (warp 0) + publish to the L2 mailbox ----
        if (warp == 0) {
            u64 k  = s_wkey[lane & 7];
            u32 h  = (u32)(k >> 32);
            u32 lo = (u32)k;
            u32 hmax = __reduce_max_sync(0xFFFFFFFFu, h);
            u32 lsel = (h == hmax) ? lo : 0u;        // max(~idx) == min idx
            u32 lmax = __reduce_max_sync(0xFFFFFFFFu, lsel);
            if (lane == 0) {
                u64 v = ((u64)hmax << 32) |
                        ((u64)(lmax & 0xFFFFu) << 16) |   // ni16 = (~idx)&0xFFFF
                        (u64)(u32)j;                       // tag
                *(volatile u64*)&g_slots[b][j & 1][c] = v;
            }
        }

        // ---- every warp polls all 16 slots (lane l < 16 owns slot l);
        //      key is carried IN the poll load (self-validating slot) ----
        u64 v = 0;
        {
            volatile const u64* slots = &g_slots[b][j & 1][0];
            bool ok;
            do {
                if (lane < CPB) v = slots[lane];
                ok = (lane >= CPB) | (((u32)v & 0xFFFFu) == (u32)j);
            } while (__ballot_sync(0xFFFFFFFFu, ok) != 0xFFFFFFFFu);
        }

        // ---- select global winner from the 16 slot values already in regs ----
        {
            u32 h   = (lane < CPB) ? (u32)(v >> 32) : 0u;       // dist bits
            u32 mid = (lane < CPB) ? (((u32)v) >> 16) : 0u;     // ni16
            u32 hmax = __reduce_max_sync(0xFFFFFFFFu, h);
            u32 msel = (h == hmax) ? mid : 0u;
            u32 mmax = __reduce_max_sync(0xFFFFFFFFu, msel);
            int widx = (int)((~mmax) & 0xFFFFu);                // idx in [0,65536)

            // ---- fetch winning centroid coords (L2 broadcast load) ----
            cx = __ldg(xb + widx);
            cy = __ldg(xb + NPTS + widx);
            cz = __ldg(xb + 2 * NPTS + widx);
        }

        if (c == 0 && tid == 0) {
            ob[j]            = cx;
            ob[MOUT + j]     = cy;
            ob[2 * MOUT + j] = cz;
        }
    }
}

extern "C" void kernel_launch(void* const* d_in, const int* in_sizes, int n_in,
                              void* d_out, int out_size)
{
    const float* x = (const float*)d_in[0];
    float* out     = (float*)d_out;
    fps_kernel<<<BATCHES * CPB, TPB>>>(x, out);
}